// round 9
// baseline (speedup 1.0000x reference)
#include <cuda_runtime.h>

#define NN      50000
#define EE      800000
#define INDIM   128
#define D       64
#define H       4
#define NR      20
#define NB      8
#define STCOLS  160
#define WSTLD   192          // Wst stride (160 cols padded)
#define WB_COLS 480          // 64 (z) + 256 (self) + 160 (st)
#define WB_LD   512          // Wbig stride

// ---- static scratch (no allocation allowed) ----
__device__ __align__(16) float g_z[NN * D];              // 12.8 MB
__device__ __align__(16) float g_st[NN * STCOLS];        // 32 MB
__device__ __align__(16) float g_Wst[D * WSTLD];         // 48 KB
__device__ __align__(16) float g_Wbig[INDIM * WB_LD];    // 256 KB
__device__ int g_deg[NN];
__device__ int g_rowptr[NN + 1];
__device__ int g_cursor[NN];
__device__ unsigned g_csr[EE];

// packed fp32x2 FMA: d = a*b + d (Blackwell)
#define FMA_F32X2(d, a, b) \
    asm("fma.rn.f32x2 %0, %1, %2, %0;" : "+l"(d) : "l"(a), "l"(b))
#define BCAST_F32X2(d, s) \
    asm("mov.b64 %0, {%1, %1};" : "=l"(d) : "f"(s))

// ---------------------------------------------------------------------------
// Wst[c][jj]: basis-combined attention weights (src part jj<80, dst part >=80)
// ---------------------------------------------------------------------------
__global__ void build_wst_kernel(const float* __restrict__ w_comp,
                                 const float* __restrict__ aw) {
    int idx = blockIdx.x * blockDim.x + threadIdx.x;
    if (idx >= D * WSTLD) return;
    int c  = idx / WSTLD;
    int jj = idx % WSTLD;
    if (jj >= STCOLS) { g_Wst[idx] = 0.f; return; }
    int r, hh, cc;
    if (jj < 80) { r = jj >> 2; hh = jj & 3; cc = c; }
    else         { int j2 = jj - 80; r = j2 >> 2; hh = j2 & 3; cc = c + D; }
    float acc = 0.f;
#pragma unroll
    for (int b = 0; b < NB; b++)
        acc += w_comp[r * NB + b] * aw[b * (2 * D * H) + cc * H + hh];
    g_Wst[idx] = acc;
}

// Wbig[k][j]: j<64 fc^T | j<320 self^T | j<480 fc^T@Wst | j<512 zero
__global__ void build_wbig_kernel(const float* __restrict__ fc_w,
                                  const float* __restrict__ self_fc_w) {
    int idx = blockIdx.x * blockDim.x + threadIdx.x;
    if (idx >= INDIM * WB_LD) return;
    int k = idx / WB_LD;
    int j = idx % WB_LD;
    float val;
    if (j < D) {
        val = fc_w[j * INDIM + k];
    } else if (j < D + H * D) {
        val = self_fc_w[(j - D) * INDIM + k];
    } else if (j < WB_COLS) {
        int jj = j - (D + H * D);
        float acc = 0.f;
#pragma unroll 8
        for (int c = 0; c < D; c++)
            acc += fc_w[c * INDIM + k] * g_Wst[c * WSTLD + jj];
        val = acc;
    } else {
        val = 0.f;
    }
    g_Wbig[idx] = val;
}

// ---------------------------------------------------------------------------
// Fused GEMM: C[N,512] = h[N,128] @ Wbig[128,512]
// BM=128, BN=64, BK=16, 256 thr, 8x4 microtile as 4 row-pair f32x2 accs.
// Double-buffered smem + register prefetch: ONE sync per k-iter; next tile's
// LDGs issue before the 16-step FMA burst (latency hidden under compute).
// Store routing: x=0 -> g_z ; x=1..4 -> d_out ; x=5..7 -> g_st (col<480)
// ---------------------------------------------------------------------------
#define BM 128
#define BN 64
#define BK 16
#define NITER (INDIM / BK)   // 8

__global__ __launch_bounds__(256) void gemm_kernel(const float* __restrict__ A,
                                                   float* __restrict__ out) {
    __shared__ __align__(16) float As[2][BK][BM + 4];
    __shared__ __align__(16) float Bs[2][BK][BN];
    const int tid = threadIdx.x;
    const int tx = tid & 15;
    const int ty = tid >> 4;
    const int rowBase = blockIdx.y * BM;
    const int colBase = blockIdx.x * BN;
    const int aRow = tid >> 1;               // 0..127
    const int aK   = (tid & 1) << 3;         // 0 or 8
    const int bK   = tid >> 4;               // 0..15
    const int bCol = (tid & 15) << 2;        // 0..60
    const int gr   = rowBase + aRow;
    const bool aOk = (gr < NN);
    const float* aBase = A + (size_t)(aOk ? gr : 0) * INDIM + aK;
    const float* bBase = g_Wbig + (size_t)bK * WB_LD + colBase + bCol;

    unsigned long long acc2[4][4];
#pragma unroll
    for (int i = 0; i < 4; i++)
#pragma unroll
        for (int j = 0; j < 4; j++) acc2[i][j] = 0ull;

    // prologue: tile 0 -> buf 0
    float4 ra0 = make_float4(0.f, 0.f, 0.f, 0.f), ra1 = ra0;
    if (aOk) {
        ra0 = *reinterpret_cast<const float4*>(aBase);
        ra1 = *reinterpret_cast<const float4*>(aBase + 4);
    }
    float4 rb = *reinterpret_cast<const float4*>(bBase);
    As[0][aK + 0][aRow] = ra0.x; As[0][aK + 1][aRow] = ra0.y;
    As[0][aK + 2][aRow] = ra0.z; As[0][aK + 3][aRow] = ra0.w;
    As[0][aK + 4][aRow] = ra1.x; As[0][aK + 5][aRow] = ra1.y;
    As[0][aK + 6][aRow] = ra1.z; As[0][aK + 7][aRow] = ra1.w;
    *reinterpret_cast<float4*>(&Bs[0][bK][bCol]) = rb;
    __syncthreads();

#pragma unroll
    for (int it = 0; it < NITER; it++) {
        const int buf = it & 1;
        // prefetch next tile into registers (LDG latency hides under FMAs)
        float4 na0 = make_float4(0.f, 0.f, 0.f, 0.f), na1 = na0, nb = na0;
        if (it + 1 < NITER) {
            int k0 = (it + 1) * BK;
            if (aOk) {
                na0 = *reinterpret_cast<const float4*>(aBase + k0);
                na1 = *reinterpret_cast<const float4*>(aBase + k0 + 4);
            }
            nb = *reinterpret_cast<const float4*>(bBase + (size_t)k0 * WB_LD);
        }

#pragma unroll
        for (int kk = 0; kk < BK; kk++) {
            ulonglong2 A01 = *reinterpret_cast<const ulonglong2*>(&As[buf][kk][ty * 8]);
            ulonglong2 A23 = *reinterpret_cast<const ulonglong2*>(&As[buf][kk][ty * 8 + 4]);
            float4 b4 = *reinterpret_cast<const float4*>(&Bs[buf][kk][tx * 4]);
            unsigned long long bb[4];
            BCAST_F32X2(bb[0], b4.x); BCAST_F32X2(bb[1], b4.y);
            BCAST_F32X2(bb[2], b4.z); BCAST_F32X2(bb[3], b4.w);
#pragma unroll
            for (int j = 0; j < 4; j++) {
                FMA_F32X2(acc2[0][j], A01.x, bb[j]);
                FMA_F32X2(acc2[1][j], A01.y, bb[j]);
                FMA_F32X2(acc2[2][j], A23.x, bb[j]);
                FMA_F32X2(acc2[3][j], A23.y, bb[j]);
            }
        }

        if (it + 1 < NITER) {
            const int nbuf = buf ^ 1;
            As[nbuf][aK + 0][aRow] = na0.x; As[nbuf][aK + 1][aRow] = na0.y;
            As[nbuf][aK + 2][aRow] = na0.z; As[nbuf][aK + 3][aRow] = na0.w;
            As[nbuf][aK + 4][aRow] = na1.x; As[nbuf][aK + 5][aRow] = na1.y;
            As[nbuf][aK + 6][aRow] = na1.z; As[nbuf][aK + 7][aRow] = na1.w;
            *reinterpret_cast<float4*>(&Bs[nbuf][bK][bCol]) = nb;
        }
        __syncthreads();
    }

    // routed store (each block column lies wholly in one destination)
#pragma unroll
    for (int ip = 0; ip < 4; ip++) {
        float2 c0 = *reinterpret_cast<float2*>(&acc2[ip][0]);
        float2 c1 = *reinterpret_cast<float2*>(&acc2[ip][1]);
        float2 c2 = *reinterpret_cast<float2*>(&acc2[ip][2]);
        float2 c3 = *reinterpret_cast<float2*>(&acc2[ip][3]);
        int row0 = rowBase + ty * 8 + ip * 2;
        int col = colBase + tx * 4;
        float4 lo = make_float4(c0.x, c1.x, c2.x, c3.x);
        float4 hi = make_float4(c0.y, c1.y, c2.y, c3.y);
        if (col < D) {
            if (row0 < NN)     *reinterpret_cast<float4*>(g_z + (size_t)row0 * D + col) = lo;
            if (row0 + 1 < NN) *reinterpret_cast<float4*>(g_z + (size_t)(row0 + 1) * D + col) = hi;
        } else if (col < D + H * D) {
            int oc = col - D;
            if (row0 < NN)     *reinterpret_cast<float4*>(out + (size_t)row0 * (H * D) + oc) = lo;
            if (row0 + 1 < NN) *reinterpret_cast<float4*>(out + (size_t)(row0 + 1) * (H * D) + oc) = hi;
        } else if (col < WB_COLS) {
            int sc = col - (D + H * D);
            if (row0 < NN)     *reinterpret_cast<float4*>(g_st + (size_t)row0 * STCOLS + sc) = lo;
            if (row0 + 1 < NN) *reinterpret_cast<float4*>(g_st + (size_t)(row0 + 1) * STCOLS + sc) = hi;
        }
    }
}

// ---------------------------------------------------------------------------
// CSR build
// ---------------------------------------------------------------------------
__global__ void zero_deg_kernel() {
    int i = blockIdx.x * blockDim.x + threadIdx.x;
    if (i < NN) g_deg[i] = 0;
}

__global__ void hist_kernel(const int* __restrict__ dst) {
    int t = blockIdx.x * blockDim.x + threadIdx.x;
    if (t * 4 >= EE) return;
    int4 d4 = *reinterpret_cast<const int4*>(dst + t * 4);
    atomicAdd(&g_deg[d4.x], 1);
    atomicAdd(&g_deg[d4.y], 1);
    atomicAdd(&g_deg[d4.z], 1);
    atomicAdd(&g_deg[d4.w], 1);
}

#define SCAN_T 1024
#define SCAN_CHUNK 49
__global__ __launch_bounds__(SCAN_T) void scan_kernel() {
    __shared__ int sums[SCAN_T];
    int t = threadIdx.x;
    int beg = t * SCAN_CHUNK;
    int end = min(NN, beg + SCAN_CHUNK);
    int s = 0;
    for (int i = beg; i < end; i++) s += g_deg[i];
    sums[t] = s;
    __syncthreads();
#pragma unroll
    for (int off = 1; off < SCAN_T; off <<= 1) {
        int v = (t >= off) ? sums[t - off] : 0;
        __syncthreads();
        sums[t] += v;
        __syncthreads();
    }
    int run = (t == 0) ? 0 : sums[t - 1];
    for (int i = beg; i < end; i++) {
        g_rowptr[i] = run;
        g_cursor[i] = run;
        run += g_deg[i];
    }
    if (t == SCAN_T - 1) g_rowptr[NN] = sums[SCAN_T - 1];
}

__global__ void scatter_kernel(const int* __restrict__ src,
                               const int* __restrict__ dst,
                               const int* __restrict__ rel) {
    int e = blockIdx.x * blockDim.x + threadIdx.x;
    if (e >= EE) return;
    int d = dst[e];
    int pos = atomicAdd(&g_cursor[d], 1);
    g_csr[pos] = (unsigned)src[e] | ((unsigned)rel[e] << 16);
}

// ---------------------------------------------------------------------------
// Aggregate: one warp per destination node, 4-edge unrolled (≈12 LDGs in
// flight). Non-atomic += into d_out (self term already there from GEMM).
// ---------------------------------------------------------------------------
__global__ __launch_bounds__(256) void aggregate_kernel(float* __restrict__ out) {
    int w = (blockIdx.x * blockDim.x + threadIdx.x) >> 5;
    if (w >= NN) return;
    int lane = threadIdx.x & 31;

    int beg = g_rowptr[w];
    int end = g_rowptr[w + 1];

    float acc[8];
#pragma unroll
    for (int i = 0; i < 8; i++) acc[i] = 0.f;

    const float* tvb = g_st + (size_t)w * STCOLS + 80;
    const int zoff = lane << 1;

    int i = beg;
    for (; i + 3 < end; i += 4) {
        unsigned p0 = __ldg(&g_csr[i]);
        unsigned p1 = __ldg(&g_csr[i + 1]);
        unsigned p2 = __ldg(&g_csr[i + 2]);
        unsigned p3 = __ldg(&g_csr[i + 3]);
        int s0 = p0 & 0xFFFFu, r0 = p0 >> 16;
        int s1 = p1 & 0xFFFFu, r1 = p1 >> 16;
        int s2 = p2 & 0xFFFFu, r2 = p2 >> 16;
        int s3 = p3 & 0xFFFFu, r3 = p3 >> 16;
        float4 sv0 = *reinterpret_cast<const float4*>(g_st + (size_t)s0 * STCOLS + (r0 << 2));
        float4 sv1 = *reinterpret_cast<const float4*>(g_st + (size_t)s1 * STCOLS + (r1 << 2));
        float4 sv2 = *reinterpret_cast<const float4*>(g_st + (size_t)s2 * STCOLS + (r2 << 2));
        float4 sv3 = *reinterpret_cast<const float4*>(g_st + (size_t)s3 * STCOLS + (r3 << 2));
        float4 tv0 = *reinterpret_cast<const float4*>(tvb + (r0 << 2));
        float4 tv1 = *reinterpret_cast<const float4*>(tvb + (r1 << 2));
        float4 tv2 = *reinterpret_cast<const float4*>(tvb + (r2 << 2));
        float4 tv3 = *reinterpret_cast<const float4*>(tvb + (r3 << 2));
        float2 z0 = *reinterpret_cast<const float2*>(g_z + (size_t)s0 * D + zoff);
        float2 z1 = *reinterpret_cast<const float2*>(g_z + (size_t)s1 * D + zoff);
        float2 z2 = *reinterpret_cast<const float2*>(g_z + (size_t)s2 * D + zoff);
        float2 z3 = *reinterpret_cast<const float2*>(g_z + (size_t)s3 * D + zoff);

#define EDGE_ACC(sv, tv, zv)                                            \
        {                                                               \
            float a0 = sv.x + tv.x, a1 = sv.y + tv.y;                   \
            float a2 = sv.z + tv.z, a3 = sv.w + tv.w;                   \
            a0 = fmaxf(a0, 0.01f * a0); a1 = fmaxf(a1, 0.01f * a1);     \
            a2 = fmaxf(a2, 0.01f * a2); a3 = fmaxf(a3, 0.01f * a3);     \
            acc[0] += a0 * zv.x; acc[1] += a0 * zv.y;                   \
            acc[2] += a1 * zv.x; acc[3] += a1 * zv.y;                   \
            acc[4] += a2 * zv.x; acc[5] += a2 * zv.y;                   \
            acc[6] += a3 * zv.x; acc[7] += a3 * zv.y;                   \
        }
        EDGE_ACC(sv0, tv0, z0)
        EDGE_ACC(sv1, tv1, z1)
        EDGE_ACC(sv2, tv2, z2)
        EDGE_ACC(sv3, tv3, z3)
    }
    for (; i < end; i++) {
        unsigned pc = __ldg(&g_csr[i]);
        int s = pc & 0xFFFFu, r = pc >> 16;
        float4 sv = *reinterpret_cast<const float4*>(g_st + (size_t)s * STCOLS + (r << 2));
        float4 tv = *reinterpret_cast<const float4*>(tvb + (r << 2));
        float2 zv = *reinterpret_cast<const float2*>(g_z + (size_t)s * D + zoff);
        EDGE_ACC(sv, tv, zv)
    }
#undef EDGE_ACC

    float* o = out + (size_t)w * (H * D) + zoff;
#pragma unroll
    for (int hh = 0; hh < H; hh++) {
        float2* op = reinterpret_cast<float2*>(o + hh * D);
        float2 cur = *op;
        cur.x += acc[hh * 2 + 0];
        cur.y += acc[hh * 2 + 1];
        *op = cur;
    }
}

// ---------------------------------------------------------------------------
extern "C" void kernel_launch(void* const* d_in, const int* in_sizes, int n_in,
                              void* d_out, int out_size) {
    const float* h_in      = (const float*)d_in[0];
    const float* fc_w      = (const float*)d_in[1];
    const float* self_fc_w = (const float*)d_in[2];
    const float* attn_w    = (const float*)d_in[3];
    const float* w_comp    = (const float*)d_in[4];
    const int*   src       = (const int*)d_in[5];
    const int*   dst       = (const int*)d_in[6];
    const int*   rel       = (const int*)d_in[7];
    float* out = (float*)d_out;

    // weight prep
    build_wst_kernel<<<(D * WSTLD + 255) / 256, 256>>>(w_comp, attn_w);
    build_wbig_kernel<<<(INDIM * WB_LD + 255) / 256, 256>>>(fc_w, self_fc_w);

    // CSR build
    zero_deg_kernel<<<(NN + 255) / 256, 256>>>();
    hist_kernel<<<(EE / 4 + 255) / 256, 256>>>(dst);
    scan_kernel<<<1, SCAN_T>>>();
    scatter_kernel<<<(EE + 255) / 256, 256>>>(src, dst, rel);

    // fused node projection (z + self + st in one pass)
    dim3 gg(WB_LD / BN, (NN + BM - 1) / BM);   // 8 x 391
    gemm_kernel<<<gg, 256>>>(h_in, out);

    // edge aggregation
    aggregate_kernel<<<(NN * 32 + 255) / 256, 256>>>(out);
}

// round 10
// speedup vs baseline: 1.1031x; 1.1031x over previous
#include <cuda_runtime.h>

#define NN      50000
#define EE      800000
#define INDIM   128
#define D       64
#define H       4
#define NR      20
#define NB      8
#define STCOLS  160
#define W1COLS  320          // 64 (z) + 256 (self)
#define WSTLD   192          // Wst stride (160 cols padded to 3x64)

// ---- static scratch (no allocation allowed) ----
__device__ __align__(16) float g_z[NN * D];              // 12.8 MB
__device__ __align__(16) float g_st[NN * STCOLS];        // 32 MB
__device__ __align__(16) float g_W1[INDIM * W1COLS];     // 160 KB
__device__ __align__(16) float g_Wst[D * WSTLD];         // 48 KB
__device__ int g_deg[NN];
__device__ int g_rowptr[NN + 1];
__device__ int g_cursor[NN];
__device__ unsigned g_csr[EE];

// packed fp32x2 FMA: d = a*b + d (Blackwell)
#define FMA_F32X2(d, a, b) \
    asm("fma.rn.f32x2 %0, %1, %2, %0;" : "+l"(d) : "l"(a), "l"(b))
#define BCAST_F32X2(d, s) \
    asm("mov.b64 %0, {%1, %1};" : "=l"(d) : "f"(s))

// ---------------------------------------------------------------------------
// Wst[c][jj]: basis-combined attention weights (src part jj<80, dst part >=80)
// ---------------------------------------------------------------------------
__global__ void build_wst_kernel(const float* __restrict__ w_comp,
                                 const float* __restrict__ aw) {
    int idx = blockIdx.x * blockDim.x + threadIdx.x;
    if (idx >= D * WSTLD) return;
    int c  = idx / WSTLD;
    int jj = idx % WSTLD;
    if (jj >= STCOLS) { g_Wst[idx] = 0.f; return; }
    int r, hh, cc;
    if (jj < 80) { r = jj >> 2; hh = jj & 3; cc = c; }
    else         { int j2 = jj - 80; r = j2 >> 2; hh = j2 & 3; cc = c + D; }
    float acc = 0.f;
#pragma unroll
    for (int b = 0; b < NB; b++)
        acc += w_comp[r * NB + b] * aw[b * (2 * D * H) + cc * H + hh];
    g_Wst[idx] = acc;
}

// W1[k][j]: j<64 -> fc_w^T ; j in [64,320) -> self_fc_w^T
__global__ void build_w1_kernel(const float* __restrict__ fc_w,
                                const float* __restrict__ self_fc_w) {
    int idx = blockIdx.x * blockDim.x + threadIdx.x;
    if (idx >= INDIM * W1COLS) return;
    int k = idx / W1COLS;
    int j = idx % W1COLS;
    g_W1[idx] = (j < D) ? fc_w[j * INDIM + k] : self_fc_w[(j - D) * INDIM + k];
}

// ---------------------------------------------------------------------------
// SGEMM: BM=128, BN=64, BK=16, 256 thr, 8x4 microtile as f32x2 row-pairs.
// Double-buffered smem + register prefetch; one __syncthreads per k-iter.
// ---------------------------------------------------------------------------
#define BM 128
#define BN 64
#define BK 16

// GEMM1: C[N,320] = h[N,128] @ W1[128,320]; cols [0,64)->g_z, rest->d_out
__global__ __launch_bounds__(256) void gemm1_kernel(const float* __restrict__ A,
                                                    float* __restrict__ out) {
    __shared__ __align__(16) float As[2][BK][BM + 4];
    __shared__ __align__(16) float Bs[2][BK][BN];
    const int tid = threadIdx.x;
    const int tx = tid & 15;
    const int ty = tid >> 4;
    const int rowBase = blockIdx.y * BM;
    const int colBase = blockIdx.x * BN;
    const int aRow = tid >> 1;
    const int aK   = (tid & 1) << 3;
    const int bK   = tid >> 4;
    const int bCol = (tid & 15) << 2;
    const int gr   = rowBase + aRow;
    const bool aOk = (gr < NN);
    const float* aBase = A + (size_t)(aOk ? gr : 0) * INDIM + aK;
    const float* bBase = g_W1 + (size_t)bK * W1COLS + colBase + bCol;
    const int NIT = INDIM / BK;   // 8

    unsigned long long acc2[4][4];
#pragma unroll
    for (int i = 0; i < 4; i++)
#pragma unroll
        for (int j = 0; j < 4; j++) acc2[i][j] = 0ull;

    // prologue: tile 0 -> buf 0
    float4 ra0 = make_float4(0.f, 0.f, 0.f, 0.f), ra1 = ra0;
    if (aOk) {
        ra0 = *reinterpret_cast<const float4*>(aBase);
        ra1 = *reinterpret_cast<const float4*>(aBase + 4);
    }
    float4 rb = *reinterpret_cast<const float4*>(bBase);
    As[0][aK + 0][aRow] = ra0.x; As[0][aK + 1][aRow] = ra0.y;
    As[0][aK + 2][aRow] = ra0.z; As[0][aK + 3][aRow] = ra0.w;
    As[0][aK + 4][aRow] = ra1.x; As[0][aK + 5][aRow] = ra1.y;
    As[0][aK + 6][aRow] = ra1.z; As[0][aK + 7][aRow] = ra1.w;
    *reinterpret_cast<float4*>(&Bs[0][bK][bCol]) = rb;
    __syncthreads();

#pragma unroll
    for (int it = 0; it < 8; it++) {
        const int buf = it & 1;
        float4 na0 = make_float4(0.f, 0.f, 0.f, 0.f), na1 = na0, nb = na0;
        if (it + 1 < NIT) {
            int k0 = (it + 1) * BK;
            if (aOk) {
                na0 = *reinterpret_cast<const float4*>(aBase + k0);
                na1 = *reinterpret_cast<const float4*>(aBase + k0 + 4);
            }
            nb = *reinterpret_cast<const float4*>(bBase + (size_t)k0 * W1COLS);
        }
#pragma unroll
        for (int kk = 0; kk < BK; kk++) {
            ulonglong2 A01 = *reinterpret_cast<const ulonglong2*>(&As[buf][kk][ty * 8]);
            ulonglong2 A23 = *reinterpret_cast<const ulonglong2*>(&As[buf][kk][ty * 8 + 4]);
            float4 b4 = *reinterpret_cast<const float4*>(&Bs[buf][kk][tx * 4]);
            unsigned long long bb[4];
            BCAST_F32X2(bb[0], b4.x); BCAST_F32X2(bb[1], b4.y);
            BCAST_F32X2(bb[2], b4.z); BCAST_F32X2(bb[3], b4.w);
#pragma unroll
            for (int j = 0; j < 4; j++) {
                FMA_F32X2(acc2[0][j], A01.x, bb[j]);
                FMA_F32X2(acc2[1][j], A01.y, bb[j]);
                FMA_F32X2(acc2[2][j], A23.x, bb[j]);
                FMA_F32X2(acc2[3][j], A23.y, bb[j]);
            }
        }
        if (it + 1 < NIT) {
            const int nbuf = buf ^ 1;
            As[nbuf][aK + 0][aRow] = na0.x; As[nbuf][aK + 1][aRow] = na0.y;
            As[nbuf][aK + 2][aRow] = na0.z; As[nbuf][aK + 3][aRow] = na0.w;
            As[nbuf][aK + 4][aRow] = na1.x; As[nbuf][aK + 5][aRow] = na1.y;
            As[nbuf][aK + 6][aRow] = na1.z; As[nbuf][aK + 7][aRow] = na1.w;
            *reinterpret_cast<float4*>(&Bs[nbuf][bK][bCol]) = nb;
            __syncthreads();
        }
    }

#pragma unroll
    for (int ip = 0; ip < 4; ip++) {
        float2 c0 = *reinterpret_cast<float2*>(&acc2[ip][0]);
        float2 c1 = *reinterpret_cast<float2*>(&acc2[ip][1]);
        float2 c2 = *reinterpret_cast<float2*>(&acc2[ip][2]);
        float2 c3 = *reinterpret_cast<float2*>(&acc2[ip][3]);
        int row0 = rowBase + ty * 8 + ip * 2;
        int col = colBase + tx * 4;
        float4 lo = make_float4(c0.x, c1.x, c2.x, c3.x);
        float4 hi = make_float4(c0.y, c1.y, c2.y, c3.y);
        if (col < D) {
            if (row0 < NN)     *reinterpret_cast<float4*>(g_z + (size_t)row0 * D + col) = lo;
            if (row0 + 1 < NN) *reinterpret_cast<float4*>(g_z + (size_t)(row0 + 1) * D + col) = hi;
        } else {
            int oc = col - D;
            if (row0 < NN)     *reinterpret_cast<float4*>(out + (size_t)row0 * (H * D) + oc) = lo;
            if (row0 + 1 < NN) *reinterpret_cast<float4*>(out + (size_t)(row0 + 1) * (H * D) + oc) = hi;
        }
    }
}

// GEMM2: st[N,160] = z[N,64] @ Wst[64,192(pad)]
__global__ __launch_bounds__(256) void gemm2_kernel() {
    __shared__ __align__(16) float As[2][BK][BM + 4];
    __shared__ __align__(16) float Bs[2][BK][BN];
    const int tid = threadIdx.x;
    const int tx = tid & 15, ty = tid >> 4;
    const int rowBase = blockIdx.y * BM;
    const int colBase = blockIdx.x * BN;
    const int aRow = tid >> 1;
    const int aK   = (tid & 1) << 3;
    const int bK   = tid >> 4;
    const int bCol = (tid & 15) << 2;
    const int gr   = rowBase + aRow;
    const bool aOk = (gr < NN);
    const float* aBase = g_z + (size_t)(aOk ? gr : 0) * D + aK;
    const float* bBase = g_Wst + (size_t)bK * WSTLD + colBase + bCol;
    const int NIT = D / BK;   // 4

    unsigned long long acc2[4][4];
#pragma unroll
    for (int i = 0; i < 4; i++)
#pragma unroll
        for (int j = 0; j < 4; j++) acc2[i][j] = 0ull;

    float4 ra0 = make_float4(0.f, 0.f, 0.f, 0.f), ra1 = ra0;
    if (aOk) {
        ra0 = *reinterpret_cast<const float4*>(aBase);
        ra1 = *reinterpret_cast<const float4*>(aBase + 4);
    }
    float4 rb = *reinterpret_cast<const float4*>(bBase);
    As[0][aK + 0][aRow] = ra0.x; As[0][aK + 1][aRow] = ra0.y;
    As[0][aK + 2][aRow] = ra0.z; As[0][aK + 3][aRow] = ra0.w;
    As[0][aK + 4][aRow] = ra1.x; As[0][aK + 5][aRow] = ra1.y;
    As[0][aK + 6][aRow] = ra1.z; As[0][aK + 7][aRow] = ra1.w;
    *reinterpret_cast<float4*>(&Bs[0][bK][bCol]) = rb;
    __syncthreads();

#pragma unroll
    for (int it = 0; it < 4; it++) {
        const int buf = it & 1;
        float4 na0 = make_float4(0.f, 0.f, 0.f, 0.f), na1 = na0, nb = na0;
        if (it + 1 < NIT) {
            int k0 = (it + 1) * BK;
            if (aOk) {
                na0 = *reinterpret_cast<const float4*>(aBase + k0);
                na1 = *reinterpret_cast<const float4*>(aBase + k0 + 4);
            }
            nb = *reinterpret_cast<const float4*>(bBase + (size_t)k0 * WSTLD);
        }
#pragma unroll
        for (int kk = 0; kk < BK; kk++) {
            ulonglong2 A01 = *reinterpret_cast<const ulonglong2*>(&As[buf][kk][ty * 8]);
            ulonglong2 A23 = *reinterpret_cast<const ulonglong2*>(&As[buf][kk][ty * 8 + 4]);
            float4 b4 = *reinterpret_cast<const float4*>(&Bs[buf][kk][tx * 4]);
            unsigned long long bb[4];
            BCAST_F32X2(bb[0], b4.x); BCAST_F32X2(bb[1], b4.y);
            BCAST_F32X2(bb[2], b4.z); BCAST_F32X2(bb[3], b4.w);
#pragma unroll
            for (int j = 0; j < 4; j++) {
                FMA_F32X2(acc2[0][j], A01.x, bb[j]);
                FMA_F32X2(acc2[1][j], A01.y, bb[j]);
                FMA_F32X2(acc2[2][j], A23.x, bb[j]);
                FMA_F32X2(acc2[3][j], A23.y, bb[j]);
            }
        }
        if (it + 1 < NIT) {
            const int nbuf = buf ^ 1;
            As[nbuf][aK + 0][aRow] = na0.x; As[nbuf][aK + 1][aRow] = na0.y;
            As[nbuf][aK + 2][aRow] = na0.z; As[nbuf][aK + 3][aRow] = na0.w;
            As[nbuf][aK + 4][aRow] = na1.x; As[nbuf][aK + 5][aRow] = na1.y;
            As[nbuf][aK + 6][aRow] = na1.z; As[nbuf][aK + 7][aRow] = na1.w;
            *reinterpret_cast<float4*>(&Bs[nbuf][bK][bCol]) = nb;
            __syncthreads();
        }
    }

#pragma unroll
    for (int ip = 0; ip < 4; ip++) {
        float2 c0 = *reinterpret_cast<float2*>(&acc2[ip][0]);
        float2 c1 = *reinterpret_cast<float2*>(&acc2[ip][1]);
        float2 c2 = *reinterpret_cast<float2*>(&acc2[ip][2]);
        float2 c3 = *reinterpret_cast<float2*>(&acc2[ip][3]);
        int row0 = rowBase + ty * 8 + ip * 2;
        int col = colBase + tx * 4;
        if (col >= STCOLS) continue;
        float4 lo = make_float4(c0.x, c1.x, c2.x, c3.x);
        float4 hi = make_float4(c0.y, c1.y, c2.y, c3.y);
        if (row0 < NN)     *reinterpret_cast<float4*>(g_st + (size_t)row0 * STCOLS + col) = lo;
        if (row0 + 1 < NN) *reinterpret_cast<float4*>(g_st + (size_t)(row0 + 1) * STCOLS + col) = hi;
    }
}

// ---------------------------------------------------------------------------
// CSR build
// ---------------------------------------------------------------------------
__global__ void zero_deg_kernel() {
    int i = blockIdx.x * blockDim.x + threadIdx.x;
    if (i < NN) g_deg[i] = 0;
}

__global__ void hist_kernel(const int* __restrict__ dst) {
    int t = blockIdx.x * blockDim.x + threadIdx.x;
    if (t * 4 >= EE) return;
    int4 d4 = *reinterpret_cast<const int4*>(dst + t * 4);
    atomicAdd(&g_deg[d4.x], 1);
    atomicAdd(&g_deg[d4.y], 1);
    atomicAdd(&g_deg[d4.z], 1);
    atomicAdd(&g_deg[d4.w], 1);
}

#define SCAN_T 1024
#define SCAN_CHUNK 49
__global__ __launch_bounds__(SCAN_T) void scan_kernel() {
    __shared__ int sums[SCAN_T];
    int t = threadIdx.x;
    int beg = t * SCAN_CHUNK;
    int end = min(NN, beg + SCAN_CHUNK);
    int s = 0;
    for (int i = beg; i < end; i++) s += g_deg[i];
    sums[t] = s;
    __syncthreads();
#pragma unroll
    for (int off = 1; off < SCAN_T; off <<= 1) {
        int v = (t >= off) ? sums[t - off] : 0;
        __syncthreads();
        sums[t] += v;
        __syncthreads();
    }
    int run = (t == 0) ? 0 : sums[t - 1];
    for (int i = beg; i < end; i++) {
        g_rowptr[i] = run;
        g_cursor[i] = run;
        run += g_deg[i];
    }
    if (t == SCAN_T - 1) g_rowptr[NN] = sums[SCAN_T - 1];
}

__global__ void scatter_kernel(const int* __restrict__ src,
                               const int* __restrict__ dst,
                               const int* __restrict__ rel) {
    int e = blockIdx.x * blockDim.x + threadIdx.x;
    if (e >= EE) return;
    int d = dst[e];
    int pos = atomicAdd(&g_cursor[d], 1);
    g_csr[pos] = (unsigned)src[e] | ((unsigned)rel[e] << 16);
}

// ---------------------------------------------------------------------------
// Aggregate: one warp per destination node, 4-edge unrolled.
// Non-atomic += into d_out (self term already there from GEMM1).
// ---------------------------------------------------------------------------
__global__ __launch_bounds__(256) void aggregate_kernel(float* __restrict__ out) {
    int w = (blockIdx.x * blockDim.x + threadIdx.x) >> 5;
    if (w >= NN) return;
    int lane = threadIdx.x & 31;

    int beg = g_rowptr[w];
    int end = g_rowptr[w + 1];

    float acc[8];
#pragma unroll
    for (int i = 0; i < 8; i++) acc[i] = 0.f;

    const float* tvb = g_st + (size_t)w * STCOLS + 80;
    const int zoff = lane << 1;

    int i = beg;
    for (; i + 3 < end; i += 4) {
        unsigned p0 = __ldg(&g_csr[i]);
        unsigned p1 = __ldg(&g_csr[i + 1]);
        unsigned p2 = __ldg(&g_csr[i + 2]);
        unsigned p3 = __ldg(&g_csr[i + 3]);
        int s0 = p0 & 0xFFFFu, r0 = p0 >> 16;
        int s1 = p1 & 0xFFFFu, r1 = p1 >> 16;
        int s2 = p2 & 0xFFFFu, r2 = p2 >> 16;
        int s3 = p3 & 0xFFFFu, r3 = p3 >> 16;
        float4 sv0 = *reinterpret_cast<const float4*>(g_st + (size_t)s0 * STCOLS + (r0 << 2));
        float4 sv1 = *reinterpret_cast<const float4*>(g_st + (size_t)s1 * STCOLS + (r1 << 2));
        float4 sv2 = *reinterpret_cast<const float4*>(g_st + (size_t)s2 * STCOLS + (r2 << 2));
        float4 sv3 = *reinterpret_cast<const float4*>(g_st + (size_t)s3 * STCOLS + (r3 << 2));
        float4 tv0 = *reinterpret_cast<const float4*>(tvb + (r0 << 2));
        float4 tv1 = *reinterpret_cast<const float4*>(tvb + (r1 << 2));
        float4 tv2 = *reinterpret_cast<const float4*>(tvb + (r2 << 2));
        float4 tv3 = *reinterpret_cast<const float4*>(tvb + (r3 << 2));
        float2 z0 = *reinterpret_cast<const float2*>(g_z + (size_t)s0 * D + zoff);
        float2 z1 = *reinterpret_cast<const float2*>(g_z + (size_t)s1 * D + zoff);
        float2 z2 = *reinterpret_cast<const float2*>(g_z + (size_t)s2 * D + zoff);
        float2 z3 = *reinterpret_cast<const float2*>(g_z + (size_t)s3 * D + zoff);

#define EDGE_ACC(sv, tv, zv)                                            \
        {                                                               \
            float a0 = sv.x + tv.x, a1 = sv.y + tv.y;                   \
            float a2 = sv.z + tv.z, a3 = sv.w + tv.w;                   \
            a0 = fmaxf(a0, 0.01f * a0); a1 = fmaxf(a1, 0.01f * a1);     \
            a2 = fmaxf(a2, 0.01f * a2); a3 = fmaxf(a3, 0.01f * a3);     \
            acc[0] += a0 * zv.x; acc[1] += a0 * zv.y;                   \
            acc[2] += a1 * zv.x; acc[3] += a1 * zv.y;                   \
            acc[4] += a2 * zv.x; acc[5] += a2 * zv.y;                   \
            acc[6] += a3 * zv.x; acc[7] += a3 * zv.y;                   \
        }
        EDGE_ACC(sv0, tv0, z0)
        EDGE_ACC(sv1, tv1, z1)
        EDGE_ACC(sv2, tv2, z2)
        EDGE_ACC(sv3, tv3, z3)
    }
    for (; i < end; i++) {
        unsigned pc = __ldg(&g_csr[i]);
        int s = pc & 0xFFFFu, r = pc >> 16;
        float4 sv = *reinterpret_cast<const float4*>(g_st + (size_t)s * STCOLS + (r << 2));
        float4 tv = *reinterpret_cast<const float4*>(tvb + (r << 2));
        float2 zv = *reinterpret_cast<const float2*>(g_z + (size_t)s * D + zoff);
        EDGE_ACC(sv, tv, zv)
    }
#undef EDGE_ACC

    float* o = out + (size_t)w * (H * D) + zoff;
#pragma unroll
    for (int hh = 0; hh < H; hh++) {
        float2* op = reinterpret_cast<float2*>(o + hh * D);
        float2 cur = *op;
        cur.x += acc[hh * 2 + 0];
        cur.y += acc[hh * 2 + 1];
        *op = cur;
    }
}

// ---------------------------------------------------------------------------
extern "C" void kernel_launch(void* const* d_in, const int* in_sizes, int n_in,
                              void* d_out, int out_size) {
    const float* h_in      = (const float*)d_in[0];
    const float* fc_w      = (const float*)d_in[1];
    const float* self_fc_w = (const float*)d_in[2];
    const float* attn_w    = (const float*)d_in[3];
    const float* w_comp    = (const float*)d_in[4];
    const int*   src       = (const int*)d_in[5];
    const int*   dst       = (const int*)d_in[6];
    const int*   rel       = (const int*)d_in[7];
    float* out = (float*)d_out;

    // weight prep
    build_wst_kernel<<<(D * WSTLD + 255) / 256, 256>>>(w_comp, attn_w);
    build_w1_kernel<<<(INDIM * W1COLS + 255) / 256, 256>>>(fc_w, self_fc_w);

    // CSR build
    zero_deg_kernel<<<(NN + 255) / 256, 256>>>();
    hist_kernel<<<(EE / 4 + 255) / 256, 256>>>(dst);
    scan_kernel<<<1, SCAN_T>>>();
    scatter_kernel<<<(EE + 255) / 256, 256>>>(src, dst, rel);

    // node projections
    dim3 g1(W1COLS / BN, (NN + BM - 1) / BM);   // 5 x 391
    gemm1_kernel<<<g1, 256>>>(h_in, out);
    dim3 g2(WSTLD / BN, (NN + BM - 1) / BM);    // 3 x 391
    gemm2_kernel<<<g2, 256>>>();

    // edge aggregation
    aggregate_kernel<<<(NN * 32 + 255) / 256, 256>>>(out);
}